// round 7
// baseline (speedup 1.0000x reference)
#include <cuda_runtime.h>
#include <cuda_bf16.h>
#include <math.h>
#include <stdint.h>

#define VOCAB 50257
#define DMEAN 1024
#define DMV   1024
#define BATCH 32
#define SEQL  128

// ---- k2 tf32 pipeline config ----
#define TM      128                       // vocab rows per block
#define KSTG    32                        // k per stage
#define NSTG    (DMV / KSTG)              // 32 stages
#define DEPTH   4
#define NBV     ((VOCAB + TM - 1) / TM)   // 393
#define AST     136                       // A k-row stride in words: banks 8k+m, conflict-free
#define BST     40                        // B n-row stride in words
#define AW_STG  (KSTG * AST)              // 4352 words per A stage
#define BW_STG  (BATCH * BST)             // 1280 words per B stage
#define K2_SMEM ((DEPTH * AW_STG + DEPTH * BW_STG) * 4)   // 90112 B

// ---- k1 (bf16 mma) config ----
#define KC      64
#define NCHUNK  16
#define AW      36
#define ABUF_W  (TM * AW)
#define BBUF_W  (BATCH * AW)
#define K1_SMEM ((2 * ABUF_W + 2 * BBUF_W) * 4)   // 46080

// Scratch (device globals — no runtime allocation allowed)
__device__ float g_h[BATCH * DMV];            // h fp32, [b][k]
__device__ float g_logits[BATCH * VOCAB];
__device__ float g_partial[BATCH];

// ---------------------------------------------------------------------------
// PTX helpers
// ---------------------------------------------------------------------------
#define LDSM4(d0, d1, d2, d3, a)                                               \
    asm volatile("ldmatrix.sync.aligned.m8n8.x4.shared.b16 {%0,%1,%2,%3}, [%4];" \
                 : "=r"(d0), "=r"(d1), "=r"(d2), "=r"(d3) : "r"(a))

#define MMA16816(c, a, bb0, bb1)                                               \
    asm volatile("mma.sync.aligned.m16n8k16.row.col.f32.bf16.bf16.f32 "        \
                 "{%0,%1,%2,%3}, {%4,%5,%6,%7}, {%8,%9}, {%0,%1,%2,%3};"       \
                 : "+f"(c[0]), "+f"(c[1]), "+f"(c[2]), "+f"(c[3])              \
                 : "r"(a[0]), "r"(a[1]), "r"(a[2]), "r"(a[3]),                 \
                   "r"(bb0), "r"(bb1))

#define MMA1688(c, a, bb0, bb1)                                                \
    asm volatile("mma.sync.aligned.m16n8k8.row.col.f32.tf32.tf32.f32 "         \
                 "{%0,%1,%2,%3}, {%4,%5,%6,%7}, {%8,%9}, {%0,%1,%2,%3};"       \
                 : "+f"(c[0]), "+f"(c[1]), "+f"(c[2]), "+f"(c[3])              \
                 : "r"(a[0]), "r"(a[1]), "r"(a[2]), "r"(a[3]),                 \
                   "r"(bb0), "r"(bb1))

__device__ __forceinline__ void cp_async16(uint32_t dst, const void* src) {
    asm volatile("cp.async.cg.shared.global [%0], [%1], 16;"
                 :: "r"(dst), "l"(src) : "memory");
}
__device__ __forceinline__ void cp_async4(uint32_t dst, const void* src) {
    asm volatile("cp.async.ca.shared.global [%0], [%1], 4;"
                 :: "r"(dst), "l"(src) : "memory");
}
__device__ __forceinline__ uint32_t lds32(uint32_t a) {
    uint32_t v;
    asm volatile("ld.shared.b32 %0, [%1];" : "=r"(v) : "r"(a));
    return v;
}
__device__ __forceinline__ uint32_t cvt_bf16x2(float hi, float lo) {
    uint32_t pk;
    asm("cvt.rn.bf16x2.f32 %0, %1, %2;" : "=r"(pk) : "f"(hi), "f"(lo));
    return pk;
}
__device__ __forceinline__ void sts32(uint32_t addr, uint32_t v) {
    asm volatile("st.shared.b32 [%0], %1;" :: "r"(addr), "r"(v));
}
#define CP_COMMIT() asm volatile("cp.async.commit_group;" ::: "memory")
#define CP_WAIT2()  asm volatile("cp.async.wait_group 2;" ::: "memory")

// ---------------------------------------------------------------------------
// Kernel 1: h = gelu(z @ W0 + b0) -> g_h fp32 [b][k].  bf16 mma, 8 blocks.
// ---------------------------------------------------------------------------
__device__ __forceinline__ void stsA_k1(uint32_t abase, int t, const float* f) {
    const uint32_t rb = abase + (uint32_t)t * (AW * 4);
#pragma unroll
    for (int s = 0; s < 32; s++) {
        int wd = (s + (t >> 3)) & 31;
        sts32(rb + wd * 4, cvt_bf16x2(f[2 * wd + 1], f[2 * wd]));
    }
}

__global__ void __launch_bounds__(128) k1_mma(const float* __restrict__ z,
                                              const float* __restrict__ W0,
                                              const float* __restrict__ b0) {
    extern __shared__ char sm[];
    const uint32_t smb = (uint32_t)__cvta_generic_to_shared(sm);
    const int t = threadIdx.x, w = t >> 5, lane = t & 31;
    const int mb0 = blockIdx.x * TM;
    const int colg = mb0 + t;

    float f[KC];
    auto loadA = [&](int c) {
        const float* p = W0 + (size_t)c * KC * DMV + colg;
#pragma unroll
        for (int j = 0; j < KC; j++) f[j] = __ldg(p + (size_t)j * DMV);
    };
    auto fillB = [&](int c, int nb) {
        const uint32_t base = smb + (2 * ABUF_W + nb * BBUF_W) * 4;
#pragma unroll
        for (int i = 0; i < 8; i++) {
            int n = (t >> 5) + 4 * i;
            int wd = t & 31;
            float2 zz = *reinterpret_cast<const float2*>(
                z + (size_t)n * DMEAN + c * KC + 2 * wd);
            sts32(base + (n * AW + wd) * 4, cvt_bf16x2(zz.y, zz.x));
        }
    };

    loadA(0);
    fillB(0, 0);
    stsA_k1(smb, t, f);
    loadA(1);
    __syncthreads();

    float acc[2][4][4];
#pragma unroll
    for (int i = 0; i < 2; i++)
#pragma unroll
        for (int j = 0; j < 4; j++)
#pragma unroll
            for (int q = 0; q < 4; q++) acc[i][j][q] = 0.f;

    for (int c = 0; c < NCHUNK; c++) {
        const int buf = c & 1, nb = buf ^ 1;
        if (c + 1 < NCHUNK) fillB(c + 1, nb);

        const uint32_t Ab = smb + buf * ABUF_W * 4;
        const uint32_t Bb = smb + (2 * ABUF_W + buf * BBUF_W) * 4;
#pragma unroll
        for (int ks = 0; ks < 4; ks++) {
            uint32_t a[2][4], bfr[2][4];
#pragma unroll
            for (int ms = 0; ms < 2; ms++) {
                int row = w * 32 + ms * 16 + (lane & 15);
                int wd = ks * 8 + ((lane >> 4) << 2);
                LDSM4(a[ms][0], a[ms][1], a[ms][2], a[ms][3],
                      Ab + (row * AW + wd) * 4);
            }
#pragma unroll
            for (int ng = 0; ng < 2; ng++) {
                int n = ng * 16 + (lane & 7) + ((lane >> 4) << 3);
                int wd = ks * 8 + (((lane >> 3) & 1) << 2);
                LDSM4(bfr[ng][0], bfr[ng][1], bfr[ng][2], bfr[ng][3],
                      Bb + (n * AW + wd) * 4);
            }
#pragma unroll
            for (int ms = 0; ms < 2; ms++)
#pragma unroll
                for (int ns = 0; ns < 4; ns++)
                    MMA16816(acc[ms][ns], a[ms],
                             bfr[ns >> 1][(ns & 1) * 2],
                             bfr[ns >> 1][(ns & 1) * 2 + 1]);
        }
        if (c + 1 < NCHUNK) {
            stsA_k1(smb + nb * ABUF_W * 4, t, f);
            if (c + 2 < NCHUNK) loadA(c + 2);
            __syncthreads();
        }
    }

#pragma unroll
    for (int ms = 0; ms < 2; ms++) {
        int m0 = mb0 + w * 32 + ms * 16 + (lane >> 2);
        int m1 = m0 + 8;
        float bv0 = b0[m0], bv1 = b0[m1];
#pragma unroll
        for (int ns = 0; ns < 4; ns++) {
            int b = ns * 8 + (lane & 3) * 2;
            float x;
            x = acc[ms][ns][0] + bv0;
            g_h[(size_t)b * DMV + m0] =
                0.5f * x * (1.f + erff(x * 0.70710678118654752f));
            x = acc[ms][ns][1] + bv0;
            g_h[(size_t)(b + 1) * DMV + m0] =
                0.5f * x * (1.f + erff(x * 0.70710678118654752f));
            x = acc[ms][ns][2] + bv1;
            g_h[(size_t)b * DMV + m1] =
                0.5f * x * (1.f + erff(x * 0.70710678118654752f));
            x = acc[ms][ns][3] + bv1;
            g_h[(size_t)(b + 1) * DMV + m1] =
                0.5f * x * (1.f + erff(x * 0.70710678118654752f));
        }
    }
}

// ---------------------------------------------------------------------------
// Kernel 2: logits = h @ W1 + b1.  TF32 mma, pure cp.async pipeline.
// A tile: 4B cp.async (W1 rows are only 4B-aligned — VOCAB is odd!).
// B tile: 16B cp.async (g_h stride 1024 floats -> 16B-aligned).
// ---------------------------------------------------------------------------
__global__ void __launch_bounds__(128) k2_mma(const float* __restrict__ W1,
                                              const float* __restrict__ b1) {
    extern __shared__ char sm[];
    const uint32_t smb = (uint32_t)__cvta_generic_to_shared(sm);
    const uint32_t bsb = smb + DEPTH * AW_STG * 4;
    const int t = threadIdx.x, w = t >> 5, lane = t & 31;
    const int vb = blockIdx.x * TM;

    // stage fill: A = 4096 words (32x 4B/thread, coalesced), B = 256 granules
    auto fill = [&](int s) {
        const int buf = s & (DEPTH - 1);
        const uint32_t Ab = smb + buf * AW_STG * 4;
        const uint32_t Bb = bsb + buf * BW_STG * 4;
        const int kr = s * KSTG;
#pragma unroll
        for (int i = 0; i < 32; i++) {
            int idx = t + i * 128;
            int k = idx >> 7, m = idx & 127;
            int vg = min(vb + m, VOCAB - 1);   // tail clamp (duplicates harmless)
            cp_async4(Ab + (uint32_t)(k * AST + m) * 4,
                      W1 + (size_t)(kr + k) * VOCAB + vg);
        }
#pragma unroll
        for (int i = 0; i < 2; i++) {
            int idx = t + i * 128;
            int n = idx >> 3, g = idx & 7;
            cp_async16(Bb + (uint32_t)(n * BST + 4 * g) * 4,
                       g_h + (size_t)n * DMV + kr + 4 * g);
        }
    };

    fill(0); CP_COMMIT();
    fill(1); CP_COMMIT();
    fill(2); CP_COMMIT();

    float acc[2][4][4];
#pragma unroll
    for (int i = 0; i < 2; i++)
#pragma unroll
        for (int j = 0; j < 4; j++)
#pragma unroll
            for (int q = 0; q < 4; q++) acc[i][j][q] = 0.f;

    for (int s = 0; s < NSTG; s++) {
        CP_WAIT2();
        __syncthreads();                 // stage s visible; buf s-1 reusable
        if (s + 3 < NSTG) fill(s + 3);
        CP_COMMIT();                     // commit every iter (group count stays in step)

        const int buf = s & (DEPTH - 1);
        const uint32_t Ab = smb + buf * AW_STG * 4;
        const uint32_t Bb = bsb + buf * BW_STG * 4;
#pragma unroll
        for (int ks = 0; ks < 4; ks++) {
            const int kb = ks * 8;
            uint32_t a[2][4], bf[4][2];
#pragma unroll
            for (int ms = 0; ms < 2; ms++) {
                int m = w * 32 + ms * 16 + (lane >> 2);
                uint32_t r0 = Ab + (uint32_t)((kb + (lane & 3)) * AST + m) * 4;
                a[ms][0] = lds32(r0);
                a[ms][1] = lds32(r0 + 8 * 4);
                a[ms][2] = lds32(r0 + 4 * AST * 4);
                a[ms][3] = lds32(r0 + (4 * AST + 8) * 4);
            }
#pragma unroll
            for (int ns = 0; ns < 4; ns++) {
                int n = ns * 8 + (lane >> 2);
                uint32_t r0 = Bb + (uint32_t)(n * BST + kb + (lane & 3)) * 4;
                bf[ns][0] = lds32(r0);
                bf[ns][1] = lds32(r0 + 4 * 4);
            }
#pragma unroll
            for (int ms = 0; ms < 2; ms++)
#pragma unroll
                for (int ns = 0; ns < 4; ns++)
                    MMA1688(acc[ms][ns], a[ms], bf[ns][0], bf[ns][1]);
        }
    }

    // epilogue: + bias, store g_logits[b][v] (guard vocab tail)
#pragma unroll
    for (int ms = 0; ms < 2; ms++) {
        int v0 = vb + w * 32 + ms * 16 + (lane >> 2);
        int v1 = v0 + 8;
        float bi0 = b1[min(v0, VOCAB - 1)];
        float bi1 = b1[min(v1, VOCAB - 1)];
#pragma unroll
        for (int ns = 0; ns < 4; ns++) {
            int b = ns * 8 + (lane & 3) * 2;
            if (v0 < VOCAB) {
                g_logits[(size_t)b * VOCAB + v0]       = acc[ms][ns][0] + bi0;
                g_logits[(size_t)(b + 1) * VOCAB + v0] = acc[ms][ns][1] + bi0;
            }
            if (v1 < VOCAB) {
                g_logits[(size_t)b * VOCAB + v1]       = acc[ms][ns][2] + bi1;
                g_logits[(size_t)(b + 1) * VOCAB + v1] = acc[ms][ns][3] + bi1;
            }
        }
    }
}

// ---------------------------------------------------------------------------
// Kernel 3: per-row logsumexp + label gather.
// ---------------------------------------------------------------------------
__global__ void __launch_bounds__(512) k3_lse(const int* __restrict__ labels) {
    const int b = blockIdx.x;
    const int tid = threadIdx.x;
    const float* row = g_logits + (size_t)b * VOCAB;
    __shared__ float red[512];

    float m = -INFINITY;
    for (int v = tid; v < VOCAB; v += 512) m = fmaxf(m, row[v]);
    red[tid] = m; __syncthreads();
    for (int s = 256; s > 0; s >>= 1) {
        if (tid < s) red[tid] = fmaxf(red[tid], red[tid + s]);
        __syncthreads();
    }
    const float M = red[0]; __syncthreads();

    float ssum = 0.f;
    for (int v = tid; v < VOCAB; v += 512) ssum += expf(row[v] - M);
    red[tid] = ssum; __syncthreads();
    for (int s = 256; s > 0; s >>= 1) {
        if (tid < s) red[tid] += red[tid + s];
        __syncthreads();
    }
    const float Ssum = red[0]; __syncthreads();

    float g = 0.f;
    if (tid < SEQL) {
        int lv = labels[b * SEQL + tid];
        lv = max(0, min(lv, VOCAB - 1));
        g = row[lv];
    }
    red[tid] = g; __syncthreads();
    for (int s = 256; s > 0; s >>= 1) {
        if (tid < s) red[tid] += red[tid + s];
        __syncthreads();
    }
    if (tid == 0) g_partial[b] = (float)SEQL * (M + logf(Ssum)) - red[0];
}

// ---------------------------------------------------------------------------
// Kernel 4: final mean.
// ---------------------------------------------------------------------------
__global__ void k4_final(float* __restrict__ out) {
    if (threadIdx.x == 0) {
        float s = 0.f;
        for (int i = 0; i < BATCH; i++) s += g_partial[i];
        out[0] = s / (float)(BATCH * SEQL);
    }
}

// ---------------------------------------------------------------------------
extern "C" void kernel_launch(void* const* d_in, const int* in_sizes, int n_in,
                              void* d_out, int out_size) {
    const float* z      = (const float*)d_in[0];
    const int*   labels = (const int*)d_in[1];
    const float* W0     = (const float*)d_in[2];
    const float* b0     = (const float*)d_in[3];
    const float* W1     = (const float*)d_in[4];
    const float* b1     = (const float*)d_in[5];
    float* out = (float*)d_out;

    cudaFuncSetAttribute(k2_mma, cudaFuncAttributeMaxDynamicSharedMemorySize,
                         K2_SMEM);

    k1_mma<<<DMV / TM, 128, K1_SMEM>>>(z, W0, b0);     // 8 blocks
    k2_mma<<<NBV, 128, K2_SMEM>>>(W1, b1);             // 393 blocks
    k3_lse<<<BATCH, 512>>>(labels);
    k4_final<<<1, 32>>>(out);
}